// round 1
// baseline (speedup 1.0000x reference)
#include <cuda_runtime.h>
#include <math.h>
#include <stdint.h>

#define NROWS 16384
#define MROWS 16384
#define DDIM  512

#define BM 128
#define BN 128
#define BK 16
#define TM 8
#define TN 8

// Scratch (no cudaMalloc allowed)
__device__ float        g_xsq[NROWS];
__device__ float        g_ysq[MROWS];
__device__ unsigned int g_min[NROWS];   // float bits of min squared distance (>=0)

// ---------------------------------------------------------------------------
// Kernel 1: per-row squared norms for x and y + init g_min to +inf
// one block (128 threads) per row index; handles x[row] and y[row] together
// ---------------------------------------------------------------------------
__global__ void kc_norms_kernel(const float* __restrict__ x,
                                const float* __restrict__ y) {
    int row = blockIdx.x;
    int tid = threadIdx.x;  // 128 threads, 4 floats each = 512
    const float4* xr = (const float4*)(x + (size_t)row * DDIM);
    const float4* yr = (const float4*)(y + (size_t)row * DDIM);
    float4 a = xr[tid];
    float4 b = yr[tid];
    float sx = a.x*a.x + a.y*a.y + a.z*a.z + a.w*a.w;
    float sy = b.x*b.x + b.y*b.y + b.z*b.z + b.w*b.w;
    #pragma unroll
    for (int o = 16; o > 0; o >>= 1) {
        sx += __shfl_down_sync(0xffffffffu, sx, o);
        sy += __shfl_down_sync(0xffffffffu, sy, o);
    }
    __shared__ float shx[4], shy[4];
    if ((tid & 31) == 0) { shx[tid >> 5] = sx; shy[tid >> 5] = sy; }
    __syncthreads();
    if (tid == 0) g_xsq[row] = shx[0] + shx[1] + shx[2] + shx[3];
    if (tid == 1) g_ysq[row] = shy[0] + shy[1] + shy[2] + shy[3];
    if (tid == 2) g_min[row] = 0x7f800000u;  // +inf
}

// ---------------------------------------------------------------------------
// Kernel 2: tiled A*B^T GEMM (dot products), fused squared-distance + row-min
// 128x128 tile per block, 16 k-slice, 8x8 per thread, 256 threads
// ---------------------------------------------------------------------------
__global__ __launch_bounds__(256, 2)
void kc_dist_kernel(const float* __restrict__ x,
                    const float* __restrict__ y) {
    __shared__ float As[BK][BM];
    __shared__ float Bs[BK][BN];

    const int bm = blockIdx.y * BM;
    const int bn = blockIdx.x * BN;
    const int tid = threadIdx.x;
    const int tx = tid & 15;        // 0..15 -> column group
    const int ty = tid >> 4;        // 0..15 -> row group

    float acc[TM][TN];
    #pragma unroll
    for (int i = 0; i < TM; i++)
        #pragma unroll
        for (int j = 0; j < TN; j++)
            acc[i][j] = 0.0f;

    // each tile: 128 rows x 16 k = 512 float4 per matrix; 256 threads x 2
    for (int k0 = 0; k0 < DDIM; k0 += BK) {
        #pragma unroll
        for (int i = 0; i < 2; i++) {
            int f   = tid + i * 256;      // 0..511
            int row = f >> 2;             // 0..127
            int kq  = (f & 3) * 4;        // 0,4,8,12
            float4 av = *(const float4*)(x + (size_t)(bm + row) * DDIM + k0 + kq);
            float4 bv = *(const float4*)(y + (size_t)(bn + row) * DDIM + k0 + kq);
            As[kq + 0][row] = av.x; As[kq + 1][row] = av.y;
            As[kq + 2][row] = av.z; As[kq + 3][row] = av.w;
            Bs[kq + 0][row] = bv.x; Bs[kq + 1][row] = bv.y;
            Bs[kq + 2][row] = bv.z; Bs[kq + 3][row] = bv.w;
        }
        __syncthreads();

        #pragma unroll
        for (int k = 0; k < BK; k++) {
            float a[TM], b[TN];
            #pragma unroll
            for (int i = 0; i < TM; i += 4) {
                float4 v = *(const float4*)&As[k][ty * TM + i];
                a[i] = v.x; a[i+1] = v.y; a[i+2] = v.z; a[i+3] = v.w;
            }
            #pragma unroll
            for (int j = 0; j < TN; j += 4) {
                float4 v = *(const float4*)&Bs[k][tx * TN + j];
                b[j] = v.x; b[j+1] = v.y; b[j+2] = v.z; b[j+3] = v.w;
            }
            #pragma unroll
            for (int i = 0; i < TM; i++)
                #pragma unroll
                for (int j = 0; j < TN; j++)
                    acc[i][j] = fmaf(a[i], b[j], acc[i][j]);
        }
        __syncthreads();
    }

    // squared distance + per-thread column-min, then block row-min, then global
    float xs[TM], ys[TN];
    #pragma unroll
    for (int i = 0; i < TM; i++) xs[i] = g_xsq[bm + ty * TM + i];
    #pragma unroll
    for (int j = 0; j < TN; j++) ys[j] = g_ysq[bn + tx * TN + j];

    __shared__ unsigned int rowmin[BM];
    if (tid < BM) rowmin[tid] = 0x7f800000u;
    __syncthreads();

    #pragma unroll
    for (int i = 0; i < TM; i++) {
        float mn = __int_as_float(0x7f800000);
        #pragma unroll
        for (int j = 0; j < TN; j++) {
            float s = fmaf(-2.0f, acc[i][j], xs[i] + ys[j]);
            s = fmaxf(s, 0.0f);
            mn = fminf(mn, s);
        }
        atomicMin(&rowmin[ty * TM + i], __float_as_uint(mn));
    }
    __syncthreads();
    if (tid < BM) atomicMin(&g_min[bm + tid], rowmin[tid]);
}

// ---------------------------------------------------------------------------
// Kernel 3: argmax over min squared distances; tie-break = lowest index
// pack (value_bits << 32) | (~idx) and max-reduce
// ---------------------------------------------------------------------------
__global__ void kc_argmax_kernel(float* __restrict__ out) {
    const int tid = threadIdx.x;  // 1024 threads
    unsigned long long best = 0ull;
    for (int i = tid; i < NROWS; i += 1024) {
        unsigned long long key =
            ((unsigned long long)g_min[i] << 32) |
            (unsigned long long)(0xffffffffu - (unsigned)i);
        if (key > best) best = key;
    }
    #pragma unroll
    for (int o = 16; o > 0; o >>= 1) {
        unsigned long long other = __shfl_down_sync(0xffffffffu, best, o);
        if (other > best) best = other;
    }
    __shared__ unsigned long long sh[32];
    if ((tid & 31) == 0) sh[tid >> 5] = best;
    __syncthreads();
    if (tid < 32) {
        best = sh[tid];
        #pragma unroll
        for (int o = 16; o > 0; o >>= 1) {
            unsigned long long other = __shfl_down_sync(0xffffffffu, best, o);
            if (other > best) best = other;
        }
        if (tid == 0) {
            unsigned int vbits = (unsigned int)(best >> 32);
            int idx = (int)(0xffffffffu - (unsigned int)(best & 0xffffffffu));
            out[0] = sqrtf(__uint_as_float(vbits));
            out[1] = (float)idx;
        }
    }
}

// ---------------------------------------------------------------------------
extern "C" void kernel_launch(void* const* d_in, const int* in_sizes, int n_in,
                              void* d_out, int out_size) {
    const float* x = (const float*)d_in[0];
    const float* y = (const float*)d_in[1];
    float* out = (float*)d_out;

    kc_norms_kernel<<<NROWS, 128>>>(x, y);

    dim3 grid(MROWS / BN, NROWS / BM);  // 128 x 128 blocks
    kc_dist_kernel<<<grid, 256>>>(x, y);

    kc_argmax_kernel<<<1, 1024>>>(out);
}

// round 4
// speedup vs baseline: 2.4081x; 2.4081x over previous
#include <cuda_runtime.h>
#include <cuda_bf16.h>
#include <math.h>
#include <stdint.h>

#define NROWS 16384
#define MROWS 16384
#define DDIM  512

// ---------------- scratch (no cudaMalloc allowed) ----------------
__device__ __align__(16) __nv_bfloat16 g_xhi[NROWS * DDIM];
__device__ __align__(16) __nv_bfloat16 g_xlo[NROWS * DDIM];
__device__ __align__(16) __nv_bfloat16 g_yhi[MROWS * DDIM];
__device__ __align__(16) __nv_bfloat16 g_ylo[MROWS * DDIM];
__device__ float        g_xsq[NROWS];
__device__ float        g_ysq[MROWS];
__device__ unsigned int g_min[NROWS];

__device__ __forceinline__ uint32_t smem_u32(const void* p) {
    uint32_t a;
    asm("{ .reg .u64 t; cvta.to.shared.u64 t, %1; cvt.u32.u64 %0, t; }"
        : "=r"(a) : "l"(p));
    return a;
}

// ---------------- GEMM config ----------------
#define BK          32                   // bf16 k per chunk
#define NCHUNK      (DDIM / BK)          // 16
#define ROWB        80                   // padded row bytes (64 data + 16 pad)
#define TILEB       (128 * ROWB)         // 10240
#define STAGEB      (4 * TILEB)          // 40960 (Ahi,Alo,Bhi,Blo)
#define STAGES      4
#define SM_DATA0    1024
#define SM_TOTAL    (SM_DATA0 + STAGES * STAGEB)   // 164864

// ---------------------------------------------------------------------------
// Kernel 1: bf16 hi/lo split + squared norms + init g_min
// ---------------------------------------------------------------------------
__global__ void kc_prep_kernel(const float* __restrict__ x,
                               const float* __restrict__ y) {
    int row = blockIdx.x;
    int tid = threadIdx.x;   // 128 threads * 4 elems = 512
    float4 a = ((const float4*)(x + (size_t)row * DDIM))[tid];
    float4 b = ((const float4*)(y + (size_t)row * DDIM))[tid];

    float av[4] = {a.x, a.y, a.z, a.w};
    float bv[4] = {b.x, b.y, b.z, b.w};
    unsigned short ah[4], al[4], bh[4], bl[4];
    float sx = 0.f, sy = 0.f;
    #pragma unroll
    for (int i = 0; i < 4; i++) {
        __nv_bfloat16 h = __float2bfloat16_rn(av[i]);
        ah[i] = __bfloat16_as_ushort(h);
        al[i] = __bfloat16_as_ushort(__float2bfloat16_rn(av[i] - __bfloat162float(h)));
        sx += av[i] * av[i];
        __nv_bfloat16 g = __float2bfloat16_rn(bv[i]);
        bh[i] = __bfloat16_as_ushort(g);
        bl[i] = __bfloat16_as_ushort(__float2bfloat16_rn(bv[i] - __bfloat162float(g)));
        sy += bv[i] * bv[i];
    }
    uint2 u;
    u.x = (uint32_t)ah[0] | ((uint32_t)ah[1] << 16); u.y = (uint32_t)ah[2] | ((uint32_t)ah[3] << 16);
    ((uint2*)(g_xhi + (size_t)row * DDIM))[tid] = u;
    u.x = (uint32_t)al[0] | ((uint32_t)al[1] << 16); u.y = (uint32_t)al[2] | ((uint32_t)al[3] << 16);
    ((uint2*)(g_xlo + (size_t)row * DDIM))[tid] = u;
    u.x = (uint32_t)bh[0] | ((uint32_t)bh[1] << 16); u.y = (uint32_t)bh[2] | ((uint32_t)bh[3] << 16);
    ((uint2*)(g_yhi + (size_t)row * DDIM))[tid] = u;
    u.x = (uint32_t)bl[0] | ((uint32_t)bl[1] << 16); u.y = (uint32_t)bl[2] | ((uint32_t)bl[3] << 16);
    ((uint2*)(g_ylo + (size_t)row * DDIM))[tid] = u;

    #pragma unroll
    for (int o = 16; o > 0; o >>= 1) {
        sx += __shfl_down_sync(0xffffffffu, sx, o);
        sy += __shfl_down_sync(0xffffffffu, sy, o);
    }
    __shared__ float shx[4], shy[4];
    if ((tid & 31) == 0) { shx[tid >> 5] = sx; shy[tid >> 5] = sy; }
    __syncthreads();
    if (tid == 0) g_xsq[row] = shx[0] + shx[1] + shx[2] + shx[3];
    if (tid == 1) g_ysq[row] = shy[0] + shy[1] + shy[2] + shy[3];
    if (tid == 2) g_min[row] = 0x7f800000u;
}

// ---------------------------------------------------------------------------
// cp.async tile loader: one 32-k chunk (4 tiles x 128 rows x 64 B)
// ---------------------------------------------------------------------------
__device__ __forceinline__ void issue_loads(uint32_t stage_smem, int c,
                                            int bm, int bn, int tid) {
    #pragma unroll
    for (int i = 0; i < 8; i++) {
        const int t = i >> 1;                     // tile id, compile-time
        const int sub = (i & 1) * 256 + tid;      // 0..511
        const int row = sub >> 2;
        const int c16 = (sub & 3) * 16;
        const char* base = (t == 0) ? (const char*)g_xhi :
                           (t == 1) ? (const char*)g_xlo :
                           (t == 2) ? (const char*)g_yhi : (const char*)g_ylo;
        const int grow = ((t < 2) ? bm : bn) + row;
        const char* src = base + (size_t)grow * (DDIM * 2) + c * (BK * 2) + c16;
        const uint32_t dst = stage_smem + t * TILEB + row * ROWB + c16;
        asm volatile("cp.async.cg.shared.global [%0], [%1], 16;"
                     :: "r"(dst), "l"(src) : "memory");
    }
    asm volatile("cp.async.commit_group;" ::: "memory");
}

__device__ __forceinline__ void ldsm4(uint32_t* r, uint32_t addr) {
    asm volatile("ldmatrix.sync.aligned.m8n8.x4.shared.b16 {%0,%1,%2,%3}, [%4];"
                 : "=r"(r[0]), "=r"(r[1]), "=r"(r[2]), "=r"(r[3]) : "r"(addr));
}
__device__ __forceinline__ void mma16816(float* d, const uint32_t* a, const uint32_t* b) {
    asm volatile("mma.sync.aligned.m16n8k16.row.col.f32.bf16.bf16.f32 "
                 "{%0,%1,%2,%3}, {%4,%5,%6,%7}, {%8,%9}, {%0,%1,%2,%3};"
                 : "+f"(d[0]), "+f"(d[1]), "+f"(d[2]), "+f"(d[3])
                 : "r"(a[0]), "r"(a[1]), "r"(a[2]), "r"(a[3]), "r"(b[0]), "r"(b[1]));
}

// ---------------------------------------------------------------------------
// Kernel 2: split-bf16 mma.sync GEMM (dot = hihi + hilo + lohi), fused min
// 128x128 CTA tile, 8 warps (2M x 4N), warp tile 64x32, 4-stage cp.async
// ---------------------------------------------------------------------------
__global__ void __launch_bounds__(256, 1)
kc_gemm_kernel() {
    extern __shared__ char smem[];
    float*        sy     = (float*)smem;                 // [128]
    unsigned int* rowmin = (unsigned int*)(smem + 512);  // [128]
    const uint32_t sdata = smem_u32(smem) + SM_DATA0;

    const int tid  = threadIdx.x;
    const int wid  = tid >> 5;
    const int lane = tid & 31;
    const int bm = blockIdx.y * 128;
    const int bn = blockIdx.x * 128;
    const int warp_m = (wid >> 2) * 64;   // 0 or 64
    const int warp_n = (wid & 3) * 32;    // 0,32,64,96

    if (tid < 128) sy[tid] = g_ysq[bn + tid];
    else           rowmin[tid - 128] = 0x7f800000u;

    // per-lane ldmatrix address components
    const int arow = ((lane >> 3) & 1) * 8 + (lane & 7);  // A: g0 r0-7, g1 r8-15
    const int acol = (lane >> 4) * 16;                    //    g2/g3 -> k8 half
    const int brow = (lane >> 4) * 8 + (lane & 7);        // B: g0/g1 n0-7, g2/g3 n8-15
    const int bcol = ((lane >> 3) & 1) * 16;              //    g1/g3 -> k8 half

    float acc[4][4][4];
    #pragma unroll
    for (int mt = 0; mt < 4; mt++)
        #pragma unroll
        for (int nt = 0; nt < 4; nt++)
            #pragma unroll
            for (int e = 0; e < 4; e++) acc[mt][nt][e] = 0.f;

    // prologue: 3 stages in flight
    issue_loads(sdata + 0 * STAGEB, 0, bm, bn, tid);
    issue_loads(sdata + 1 * STAGEB, 1, bm, bn, tid);
    issue_loads(sdata + 2 * STAGEB, 2, bm, bn, tid);

    #pragma unroll 1
    for (int c = 0; c < NCHUNK; c++) {
        asm volatile("cp.async.wait_group 2;" ::: "memory");
        __syncthreads();

        if (c + 3 < NCHUNK)
            issue_loads(sdata + ((c + 3) & 3) * STAGEB, c + 3, bm, bn, tid);
        else
            asm volatile("cp.async.commit_group;" ::: "memory");

        const uint32_t st  = sdata + (c & 3) * STAGEB;
        const uint32_t Ahi = st;
        const uint32_t Alo = st + TILEB;
        const uint32_t Bhi = st + 2 * TILEB;
        const uint32_t Blo = st + 3 * TILEB;

        #pragma unroll
        for (int kk = 0; kk < 2; kk++) {      // two k16 halves of BK=32
            const int colb = kk * 32;
            uint32_t ah[4][4], al[4][4], bh[4][2], bl[4][2];
            #pragma unroll
            for (int mt = 0; mt < 4; mt++) {
                const uint32_t off = (uint32_t)(warp_m + mt * 16 + arow) * ROWB + colb + acol;
                ldsm4(ah[mt], Ahi + off);
                ldsm4(al[mt], Alo + off);
            }
            #pragma unroll
            for (int q = 0; q < 2; q++) {
                const uint32_t off = (uint32_t)(warp_n + q * 16 + brow) * ROWB + colb + bcol;
                uint32_t r[4];
                ldsm4(r, Bhi + off);
                bh[2*q][0] = r[0]; bh[2*q][1] = r[1]; bh[2*q+1][0] = r[2]; bh[2*q+1][1] = r[3];
                ldsm4(r, Blo + off);
                bl[2*q][0] = r[0]; bl[2*q][1] = r[1]; bl[2*q+1][0] = r[2]; bl[2*q+1][1] = r[3];
            }
            #pragma unroll
            for (int mt = 0; mt < 4; mt++)
                #pragma unroll
                for (int nt = 0; nt < 4; nt++) {
                    mma16816(acc[mt][nt], ah[mt], bh[nt]);
                    mma16816(acc[mt][nt], ah[mt], bl[nt]);
                    mma16816(acc[mt][nt], al[mt], bh[nt]);
                }
        }
    }
    __syncthreads();

    // epilogue: fused squared-distance row-min
    #pragma unroll
    for (int mt = 0; mt < 4; mt++) {
        #pragma unroll
        for (int h = 0; h < 2; h++) {
            const int lrow = warp_m + mt * 16 + (lane >> 2) + h * 8;
            float mn = __int_as_float(0x7f800000);
            #pragma unroll
            for (int nt = 0; nt < 4; nt++) {
                #pragma unroll
                for (int e = 0; e < 2; e++) {
                    const int col = warp_n + nt * 8 + (lane & 3) * 2 + e;
                    mn = fminf(mn, fmaf(-2.0f, acc[mt][nt][h * 2 + e], sy[col]));
                }
            }
            mn = fminf(mn, __shfl_xor_sync(0xffffffffu, mn, 1));
            mn = fminf(mn, __shfl_xor_sync(0xffffffffu, mn, 2));
            if ((lane & 3) == 0) {
                float s = fmaxf(g_xsq[bm + lrow] + mn, 0.0f);
                atomicMin(&rowmin[lrow], __float_as_uint(s));
            }
        }
    }
    __syncthreads();
    if (tid < 128) atomicMin(&g_min[bm + tid], rowmin[tid]);
}

// ---------------------------------------------------------------------------
// Kernel 3: argmax over min squared distances (tie-break lowest index)
// ---------------------------------------------------------------------------
__global__ void kc_argmax_kernel(float* __restrict__ out) {
    const int tid = threadIdx.x;  // 1024
    unsigned long long best = 0ull;
    for (int i = tid; i < NROWS; i += 1024) {
        unsigned long long key = ((unsigned long long)g_min[i] << 32) |
                                 (unsigned long long)(0xffffffffu - (unsigned)i);
        if (key > best) best = key;
    }
    #pragma unroll
    for (int o = 16; o > 0; o >>= 1) {
        unsigned long long v = __shfl_down_sync(0xffffffffu, best, o);
        if (v > best) best = v;
    }
    __shared__ unsigned long long sh[32];
    if ((tid & 31) == 0) sh[tid >> 5] = best;
    __syncthreads();
    if (tid < 32) {
        best = sh[tid];
        #pragma unroll
        for (int o = 16; o > 0; o >>= 1) {
            unsigned long long v = __shfl_down_sync(0xffffffffu, best, o);
            if (v > best) best = v;
        }
        if (tid == 0) {
            unsigned int vbits = (unsigned int)(best >> 32);
            int idx = (int)(0xffffffffu - (unsigned int)(best & 0xffffffffu));
            out[0] = sqrtf(__uint_as_float(vbits));
            out[1] = (float)idx;
        }
    }
}

// ---------------------------------------------------------------------------
extern "C" void kernel_launch(void* const* d_in, const int* in_sizes, int n_in,
                              void* d_out, int out_size) {
    const float* x = (const float*)d_in[0];
    const float* y = (const float*)d_in[1];
    float* out = (float*)d_out;

    cudaFuncSetAttribute(kc_gemm_kernel,
                         cudaFuncAttributeMaxDynamicSharedMemorySize, SM_TOTAL);

    kc_prep_kernel<<<NROWS, 128>>>(x, y);

    dim3 grid(MROWS / 128, NROWS / 128);
    kc_gemm_kernel<<<grid, 256, SM_TOTAL>>>();

    kc_argmax_kernel<<<1, 1024>>>(out);
}

// round 5
// speedup vs baseline: 3.0040x; 1.2475x over previous
#include <cuda_runtime.h>
#include <cuda_bf16.h>
#include <math.h>
#include <stdint.h>

#define NROWS 16384
#define MROWS 16384
#define DDIM  512

// ---------------- scratch (no cudaMalloc allowed) ----------------
__device__ __align__(16) __nv_bfloat16 g_xhi[NROWS * DDIM];
__device__ __align__(16) __nv_bfloat16 g_xlo[NROWS * DDIM];
__device__ __align__(16) __nv_bfloat16 g_yhi[MROWS * DDIM];
__device__ __align__(16) __nv_bfloat16 g_ylo[MROWS * DDIM];
__device__ float        g_xsq[NROWS];
__device__ float        g_ysq[MROWS];
__device__ unsigned int g_min[NROWS];

__device__ __forceinline__ uint32_t smem_u32(const void* p) {
    uint32_t a;
    asm("{ .reg .u64 t; cvta.to.shared.u64 t, %1; cvt.u32.u64 %0, t; }"
        : "=r"(a) : "l"(p));
    return a;
}

// ---------------- GEMM config ----------------
#define BK          32                   // bf16 k per chunk
#define NCHUNK      (DDIM / BK)          // 16
#define ROWB        80                   // padded row bytes (64 data + 16 pad)
#define TILEB       (128 * ROWB)         // 10240
#define STAGEB      (4 * TILEB)          // 40960 (Ahi,Alo,Bhi,Blo)
#define STAGES      2
#define SM_DATA0    1024
#define SM_TOTAL    (SM_DATA0 + STAGES * STAGEB)   // 82944 -> 2 CTAs/SM

// ---------------------------------------------------------------------------
// Kernel 1: bf16 hi/lo split + squared norms + init g_min
// ---------------------------------------------------------------------------
__global__ void kc_prep_kernel(const float* __restrict__ x,
                               const float* __restrict__ y) {
    int row = blockIdx.x;
    int tid = threadIdx.x;   // 128 threads * 4 elems = 512
    float4 a = ((const float4*)(x + (size_t)row * DDIM))[tid];
    float4 b = ((const float4*)(y + (size_t)row * DDIM))[tid];

    float av[4] = {a.x, a.y, a.z, a.w};
    float bv[4] = {b.x, b.y, b.z, b.w};
    unsigned short ah[4], al[4], bh[4], bl[4];
    float sx = 0.f, sy = 0.f;
    #pragma unroll
    for (int i = 0; i < 4; i++) {
        __nv_bfloat16 h = __float2bfloat16_rn(av[i]);
        ah[i] = __bfloat16_as_ushort(h);
        al[i] = __bfloat16_as_ushort(__float2bfloat16_rn(av[i] - __bfloat162float(h)));
        sx += av[i] * av[i];
        __nv_bfloat16 g = __float2bfloat16_rn(bv[i]);
        bh[i] = __bfloat16_as_ushort(g);
        bl[i] = __bfloat16_as_ushort(__float2bfloat16_rn(bv[i] - __bfloat162float(g)));
        sy += bv[i] * bv[i];
    }
    uint2 u;
    u.x = (uint32_t)ah[0] | ((uint32_t)ah[1] << 16); u.y = (uint32_t)ah[2] | ((uint32_t)ah[3] << 16);
    ((uint2*)(g_xhi + (size_t)row * DDIM))[tid] = u;
    u.x = (uint32_t)al[0] | ((uint32_t)al[1] << 16); u.y = (uint32_t)al[2] | ((uint32_t)al[3] << 16);
    ((uint2*)(g_xlo + (size_t)row * DDIM))[tid] = u;
    u.x = (uint32_t)bh[0] | ((uint32_t)bh[1] << 16); u.y = (uint32_t)bh[2] | ((uint32_t)bh[3] << 16);
    ((uint2*)(g_yhi + (size_t)row * DDIM))[tid] = u;
    u.x = (uint32_t)bl[0] | ((uint32_t)bl[1] << 16); u.y = (uint32_t)bl[2] | ((uint32_t)bl[3] << 16);
    ((uint2*)(g_ylo + (size_t)row * DDIM))[tid] = u;

    #pragma unroll
    for (int o = 16; o > 0; o >>= 1) {
        sx += __shfl_down_sync(0xffffffffu, sx, o);
        sy += __shfl_down_sync(0xffffffffu, sy, o);
    }
    __shared__ float shx[4], shy[4];
    if ((tid & 31) == 0) { shx[tid >> 5] = sx; shy[tid >> 5] = sy; }
    __syncthreads();
    if (tid == 0) g_xsq[row] = shx[0] + shx[1] + shx[2] + shx[3];
    if (tid == 1) g_ysq[row] = shy[0] + shy[1] + shy[2] + shy[3];
    if (tid == 2) g_min[row] = 0x7f800000u;
}

// ---------------------------------------------------------------------------
// cp.async tile loader: one 32-k chunk (4 tiles x 128 rows x 64 B)
// ---------------------------------------------------------------------------
__device__ __forceinline__ void issue_loads(uint32_t stage_smem, int c,
                                            int bm, int bn, int tid) {
    #pragma unroll
    for (int i = 0; i < 8; i++) {
        const int t = i >> 1;                     // tile id, compile-time
        const int sub = (i & 1) * 256 + tid;      // 0..511
        const int row = sub >> 2;
        const int c16 = (sub & 3) * 16;
        const char* base = (t == 0) ? (const char*)g_xhi :
                           (t == 1) ? (const char*)g_xlo :
                           (t == 2) ? (const char*)g_yhi : (const char*)g_ylo;
        const int grow = ((t < 2) ? bm : bn) + row;
        const char* src = base + (size_t)grow * (DDIM * 2) + c * (BK * 2) + c16;
        const uint32_t dst = stage_smem + t * TILEB + row * ROWB + c16;
        asm volatile("cp.async.cg.shared.global [%0], [%1], 16;"
                     :: "r"(dst), "l"(src) : "memory");
    }
    asm volatile("cp.async.commit_group;" ::: "memory");
}

__device__ __forceinline__ void ldsm4(uint32_t* r, uint32_t addr) {
    asm volatile("ldmatrix.sync.aligned.m8n8.x4.shared.b16 {%0,%1,%2,%3}, [%4];"
                 : "=r"(r[0]), "=r"(r[1]), "=r"(r[2]), "=r"(r[3]) : "r"(addr));
}
__device__ __forceinline__ void mma16816(float* d, const uint32_t* a, const uint32_t* b) {
    asm volatile("mma.sync.aligned.m16n8k16.row.col.f32.bf16.bf16.f32 "
                 "{%0,%1,%2,%3}, {%4,%5,%6,%7}, {%8,%9}, {%0,%1,%2,%3};"
                 : "+f"(d[0]), "+f"(d[1]), "+f"(d[2]), "+f"(d[3])
                 : "r"(a[0]), "r"(a[1]), "r"(a[2]), "r"(a[3]), "r"(b[0]), "r"(b[1]));
}

// ---------------------------------------------------------------------------
// Kernel 2: split-bf16 mma.sync GEMM (dot = hihi + hilo + lohi), fused min
// 128x128 CTA tile, 8 warps (2M x 4N), warp tile 64x32, 2-stage + 2 CTAs/SM
// ---------------------------------------------------------------------------
__global__ void __launch_bounds__(256, 2)
kc_gemm_kernel() {
    extern __shared__ char smem[];
    float*        sy     = (float*)smem;                 // [128]
    unsigned int* rowmin = (unsigned int*)(smem + 512);  // [128]
    const uint32_t sdata = smem_u32(smem) + SM_DATA0;

    const int tid  = threadIdx.x;
    const int wid  = tid >> 5;
    const int lane = tid & 31;
    const int bm = blockIdx.y * 128;
    const int bn = blockIdx.x * 128;
    const int warp_m = (wid >> 2) * 64;   // 0 or 64
    const int warp_n = (wid & 3) * 32;    // 0,32,64,96

    if (tid < 128) sy[tid] = g_ysq[bn + tid];
    else           rowmin[tid - 128] = 0x7f800000u;

    // per-lane ldmatrix address components
    const int arow = ((lane >> 3) & 1) * 8 + (lane & 7);  // A: g0 r0-7, g1 r8-15
    const int acol = (lane >> 4) * 16;                    //    g2/g3 -> k8 half
    const int brow = (lane >> 4) * 8 + (lane & 7);        // B: g0/g1 n0-7, g2/g3 n8-15
    const int bcol = ((lane >> 3) & 1) * 16;              //    g1/g3 -> k8 half

    float acc[4][4][4];
    #pragma unroll
    for (int mt = 0; mt < 4; mt++)
        #pragma unroll
        for (int nt = 0; nt < 4; nt++)
            #pragma unroll
            for (int e = 0; e < 4; e++) acc[mt][nt][e] = 0.f;

    issue_loads(sdata, 0, bm, bn, tid);

    #pragma unroll 1
    for (int c = 0; c < NCHUNK; c++) {
        if (c + 1 < NCHUNK)
            issue_loads(sdata + ((c + 1) & 1) * STAGEB, c + 1, bm, bn, tid);
        else
            asm volatile("cp.async.commit_group;" ::: "memory");
        asm volatile("cp.async.wait_group 1;" ::: "memory");
        __syncthreads();

        const uint32_t st  = sdata + (c & 1) * STAGEB;
        const uint32_t Ahi = st;
        const uint32_t Alo = st + TILEB;
        const uint32_t Bhi = st + 2 * TILEB;
        const uint32_t Blo = st + 3 * TILEB;

        #pragma unroll
        for (int kk = 0; kk < 2; kk++) {      // two k16 halves of BK=32
            const int colb = kk * 32;
            uint32_t bh[4][2], bl[4][2];
            #pragma unroll
            for (int q = 0; q < 2; q++) {
                const uint32_t off = (uint32_t)(warp_n + q * 16 + brow) * ROWB + colb + bcol;
                uint32_t r[4];
                ldsm4(r, Bhi + off);
                bh[2*q][0] = r[0]; bh[2*q][1] = r[1]; bh[2*q+1][0] = r[2]; bh[2*q+1][1] = r[3];
                ldsm4(r, Blo + off);
                bl[2*q][0] = r[0]; bl[2*q][1] = r[1]; bl[2*q+1][0] = r[2]; bl[2*q+1][1] = r[3];
            }
            #pragma unroll
            for (int mt = 0; mt < 4; mt++) {
                uint32_t ah[4], al[4];
                const uint32_t off = (uint32_t)(warp_m + mt * 16 + arow) * ROWB + colb + acol;
                ldsm4(ah, Ahi + off);
                ldsm4(al, Alo + off);
                #pragma unroll
                for (int nt = 0; nt < 4; nt++) {
                    mma16816(acc[mt][nt], ah, bh[nt]);
                    mma16816(acc[mt][nt], ah, bl[nt]);
                    mma16816(acc[mt][nt], al, bh[nt]);
                }
            }
        }
        __syncthreads();
    }

    // epilogue: fused squared-distance row-min
    #pragma unroll
    for (int mt = 0; mt < 4; mt++) {
        #pragma unroll
        for (int h = 0; h < 2; h++) {
            const int lrow = warp_m + mt * 16 + (lane >> 2) + h * 8;
            float mn = __int_as_float(0x7f800000);
            #pragma unroll
            for (int nt = 0; nt < 4; nt++) {
                #pragma unroll
                for (int e = 0; e < 2; e++) {
                    const int col = warp_n + nt * 8 + (lane & 3) * 2 + e;
                    mn = fminf(mn, fmaf(-2.0f, acc[mt][nt][h * 2 + e], sy[col]));
                }
            }
            mn = fminf(mn, __shfl_xor_sync(0xffffffffu, mn, 1));
            mn = fminf(mn, __shfl_xor_sync(0xffffffffu, mn, 2));
            if ((lane & 3) == 0) {
                float s = fmaxf(g_xsq[bm + lrow] + mn, 0.0f);
                atomicMin(&rowmin[lrow], __float_as_uint(s));
            }
        }
    }
    __syncthreads();
    if (tid < 128) atomicMin(&g_min[bm + tid], rowmin[tid]);
}

// ---------------------------------------------------------------------------
// Kernel 3: argmax over min squared distances (tie-break lowest index)
// ---------------------------------------------------------------------------
__global__ void kc_argmax_kernel(float* __restrict__ out) {
    const int tid = threadIdx.x;  // 1024
    unsigned long long best = 0ull;
    for (int i = tid; i < NROWS; i += 1024) {
        unsigned long long key = ((unsigned long long)g_min[i] << 32) |
                                 (unsigned long long)(0xffffffffu - (unsigned)i);
        if (key > best) best = key;
    }
    #pragma unroll
    for (int o = 16; o > 0; o >>= 1) {
        unsigned long long v = __shfl_down_sync(0xffffffffu, best, o);
        if (v > best) best = v;
    }
    __shared__ unsigned long long sh[32];
    if ((tid & 31) == 0) sh[tid >> 5] = best;
    __syncthreads();
    if (tid < 32) {
        best = sh[tid];
        #pragma unroll
        for (int o = 16; o > 0; o >>= 1) {
            unsigned long long v = __shfl_down_sync(0xffffffffu, best, o);
            if (v > best) best = v;
        }
        if (tid == 0) {
            unsigned int vbits = (unsigned int)(best >> 32);
            int idx = (int)(0xffffffffu - (unsigned int)(best & 0xffffffffu));
            out[0] = sqrtf(__uint_as_float(vbits));
            out[1] = (float)idx;
        }
    }
}

// ---------------------------------------------------------------------------
extern "C" void kernel_launch(void* const* d_in, const int* in_sizes, int n_in,
                              void* d_out, int out_size) {
    const float* x = (const float*)d_in[0];
    const float* y = (const float*)d_in[1];
    float* out = (float*)d_out;

    cudaFuncSetAttribute(kc_gemm_kernel,
                         cudaFuncAttributeMaxDynamicSharedMemorySize, SM_TOTAL);

    kc_prep_kernel<<<NROWS, 128>>>(x, y);

    dim3 grid(MROWS / 128, NROWS / 128);
    kc_gemm_kernel<<<grid, 256, SM_TOTAL>>>();

    kc_argmax_kernel<<<1, 1024>>>(out);
}

// round 6
// speedup vs baseline: 3.4925x; 1.1626x over previous
#include <cuda_runtime.h>
#include <cuda_bf16.h>
#include <math.h>
#include <stdint.h>

#define NROWS 16384
#define MROWS 16384
#define DDIM  512

// ---------------- scratch (no cudaMalloc allowed) ----------------
__device__ __align__(16) __nv_bfloat16 g_xhi[NROWS * DDIM];
__device__ __align__(16) __nv_bfloat16 g_xlo[NROWS * DDIM];
__device__ __align__(16) __nv_bfloat16 g_yhi[MROWS * DDIM];
__device__ __align__(16) __nv_bfloat16 g_ylo[MROWS * DDIM];
__device__ float        g_xsq[NROWS];
__device__ float        g_ysq[MROWS];
__device__ unsigned int g_min[NROWS];

__device__ __forceinline__ uint32_t smem_u32(const void* p) {
    uint32_t a;
    asm("{ .reg .u64 t; cvta.to.shared.u64 t, %1; cvt.u32.u64 %0, t; }"
        : "=r"(a) : "l"(p));
    return a;
}

// ---------------- GEMM config ----------------
#define BK          32                   // bf16 k per chunk = 64 B rows (swizzled)
#define NCHUNK      (DDIM / BK)          // 16
#define ROWB        64                   // native row bytes, XOR-swizzled
#define TILEB       (128 * ROWB)         // 8192
#define STAGEB      (4 * TILEB)          // 32768 (Ahi, Alo, Bhi, Blo)
#define STAGES      3
#define SM_DATA0    1024
#define SM_TOTAL    (SM_DATA0 + STAGES * STAGEB)   // 99328 -> 2 CTAs/SM

// swizzle: 16B chunk index XORed with (row>>1)&3  (conflict-free, 16B aligned)
#define SWZ64(row, col) ((uint32_t)(row) * 64u + \
    ((((uint32_t)(col) >> 4) ^ (((uint32_t)(row) >> 1) & 3u)) << 4) + ((uint32_t)(col) & 15u))

// ---------------------------------------------------------------------------
// Kernel 1: bf16 hi/lo split + squared norms + init g_min
// ---------------------------------------------------------------------------
__global__ void kc_prep_kernel(const float* __restrict__ x,
                               const float* __restrict__ y) {
    int row = blockIdx.x;
    int tid = threadIdx.x;   // 128 threads * 4 elems = 512
    float4 a = ((const float4*)(x + (size_t)row * DDIM))[tid];
    float4 b = ((const float4*)(y + (size_t)row * DDIM))[tid];

    float av[4] = {a.x, a.y, a.z, a.w};
    float bv[4] = {b.x, b.y, b.z, b.w};
    unsigned short ah[4], al[4], bh[4], bl[4];
    float sx = 0.f, sy = 0.f;
    #pragma unroll
    for (int i = 0; i < 4; i++) {
        __nv_bfloat16 h = __float2bfloat16_rn(av[i]);
        ah[i] = __bfloat16_as_ushort(h);
        al[i] = __bfloat16_as_ushort(__float2bfloat16_rn(av[i] - __bfloat162float(h)));
        sx += av[i] * av[i];
        __nv_bfloat16 g = __float2bfloat16_rn(bv[i]);
        bh[i] = __bfloat16_as_ushort(g);
        bl[i] = __bfloat16_as_ushort(__float2bfloat16_rn(bv[i] - __bfloat162float(g)));
        sy += bv[i] * bv[i];
    }
    uint2 u;
    u.x = (uint32_t)ah[0] | ((uint32_t)ah[1] << 16); u.y = (uint32_t)ah[2] | ((uint32_t)ah[3] << 16);
    ((uint2*)(g_xhi + (size_t)row * DDIM))[tid] = u;
    u.x = (uint32_t)al[0] | ((uint32_t)al[1] << 16); u.y = (uint32_t)al[2] | ((uint32_t)al[3] << 16);
    ((uint2*)(g_xlo + (size_t)row * DDIM))[tid] = u;
    u.x = (uint32_t)bh[0] | ((uint32_t)bh[1] << 16); u.y = (uint32_t)bh[2] | ((uint32_t)bh[3] << 16);
    ((uint2*)(g_yhi + (size_t)row * DDIM))[tid] = u;
    u.x = (uint32_t)bl[0] | ((uint32_t)bl[1] << 16); u.y = (uint32_t)bl[2] | ((uint32_t)bl[3] << 16);
    ((uint2*)(g_ylo + (size_t)row * DDIM))[tid] = u;

    #pragma unroll
    for (int o = 16; o > 0; o >>= 1) {
        sx += __shfl_down_sync(0xffffffffu, sx, o);
        sy += __shfl_down_sync(0xffffffffu, sy, o);
    }
    __shared__ float shx[4], shy[4];
    if ((tid & 31) == 0) { shx[tid >> 5] = sx; shy[tid >> 5] = sy; }
    __syncthreads();
    if (tid == 0) g_xsq[row] = shx[0] + shx[1] + shx[2] + shx[3];
    if (tid == 1) g_ysq[row] = shy[0] + shy[1] + shy[2] + shy[3];
    if (tid == 2) g_min[row] = 0x7f800000u;
}

// ---------------------------------------------------------------------------
// cp.async tile loader: one 32-k chunk (4 planes x 128 rows x 64 B, swizzled)
// ---------------------------------------------------------------------------
__device__ __forceinline__ void issue_loads(uint32_t stage_smem, int c,
                                            int bm, int bn, int tid) {
    #pragma unroll
    for (int i = 0; i < 8; i++) {
        const int t = i >> 1;                     // plane id, compile-time
        const int sub = (i & 1) * 256 + tid;      // 0..511 (chunk-of-16B id in plane)
        const int row = sub >> 2;
        const int ch  = (sub & 3) * 16;
        const char* base = (t == 0) ? (const char*)g_xhi :
                           (t == 1) ? (const char*)g_xlo :
                           (t == 2) ? (const char*)g_yhi : (const char*)g_ylo;
        const int grow = ((t < 2) ? bm : bn) + row;
        const char* src = base + (size_t)grow * (DDIM * 2) + c * (BK * 2) + ch;
        const uint32_t dst = stage_smem + t * TILEB + SWZ64(row, ch);
        asm volatile("cp.async.cg.shared.global [%0], [%1], 16;"
                     :: "r"(dst), "l"(src) : "memory");
    }
    asm volatile("cp.async.commit_group;" ::: "memory");
}

__device__ __forceinline__ void ldsm4(uint32_t* r, uint32_t addr) {
    asm volatile("ldmatrix.sync.aligned.m8n8.x4.shared.b16 {%0,%1,%2,%3}, [%4];"
                 : "=r"(r[0]), "=r"(r[1]), "=r"(r[2]), "=r"(r[3]) : "r"(addr));
}
__device__ __forceinline__ void mma16816(float* d, const uint32_t* a, const uint32_t* b) {
    asm volatile("mma.sync.aligned.m16n8k16.row.col.f32.bf16.bf16.f32 "
                 "{%0,%1,%2,%3}, {%4,%5,%6,%7}, {%8,%9}, {%0,%1,%2,%3};"
                 : "+f"(d[0]), "+f"(d[1]), "+f"(d[2]), "+f"(d[3])
                 : "r"(a[0]), "r"(a[1]), "r"(a[2]), "r"(a[3]), "r"(b[0]), "r"(b[1]));
}

// ---------------------------------------------------------------------------
// Kernel 2: split-bf16 mma.sync GEMM (dot = hihi + hilo + lohi), fused min
// 128x128 CTA, 8 warps (2M x 4N), warp 64x32, 3-stage + 2 CTAs/SM, 1 sync/chunk
// ---------------------------------------------------------------------------
__global__ void __launch_bounds__(256, 2)
kc_gemm_kernel() {
    extern __shared__ char smem[];
    float*        sy     = (float*)smem;                 // [128]
    unsigned int* rowmin = (unsigned int*)(smem + 512);  // [128]
    const uint32_t sdata = smem_u32(smem) + SM_DATA0;

    const int tid  = threadIdx.x;
    const int wid  = tid >> 5;
    const int lane = tid & 31;
    const int bm = blockIdx.y * 128;
    const int bn = blockIdx.x * 128;
    const int warp_m = (wid >> 2) * 64;   // 0 or 64
    const int warp_n = (wid & 3) * 32;    // 0,32,64,96

    if (tid < 128) sy[tid] = g_ysq[bn + tid];
    else           rowmin[tid - 128] = 0x7f800000u;

    // per-lane ldmatrix row/col components
    const int arow = ((lane >> 3) & 1) * 8 + (lane & 7);  // A: g0 r0-7, g1 r8-15
    const int acol = (lane >> 4) * 16;                    //    g2/g3 -> k8 half
    const int brow = (lane >> 4) * 8 + (lane & 7);        // B: g0/g1 n0-7, g2/g3 n8-15
    const int bcol = ((lane >> 3) & 1) * 16;              //    g1/g3 -> k8 half

    // precomputed swizzled in-plane offsets (loop-invariant)
    uint32_t aoff[2][4], boff[2][2];
    #pragma unroll
    for (int kk = 0; kk < 2; kk++) {
        const int colb = kk * 32;
        #pragma unroll
        for (int mt = 0; mt < 4; mt++)
            aoff[kk][mt] = SWZ64(warp_m + mt * 16 + arow, colb + acol);
        #pragma unroll
        for (int q = 0; q < 2; q++)
            boff[kk][q] = SWZ64(warp_n + q * 16 + brow, colb + bcol);
    }

    float acc[4][4][4];
    #pragma unroll
    for (int mt = 0; mt < 4; mt++)
        #pragma unroll
        for (int nt = 0; nt < 4; nt++)
            #pragma unroll
            for (int e = 0; e < 4; e++) acc[mt][nt][e] = 0.f;

    issue_loads(sdata + 0 * STAGEB, 0, bm, bn, tid);
    issue_loads(sdata + 1 * STAGEB, 1, bm, bn, tid);

    int stage = 0, nstage = 2;   // stage of chunk c; stage to fill with c+2
    #pragma unroll 1
    for (int c = 0; c < NCHUNK; c++) {
        asm volatile("cp.async.wait_group 1;" ::: "memory");
        __syncthreads();   // chunk c visible to all; all warps done with chunk c-1

        if (c + 2 < NCHUNK)
            issue_loads(sdata + nstage * STAGEB, c + 2, bm, bn, tid);
        else
            asm volatile("cp.async.commit_group;" ::: "memory");

        const uint32_t st  = sdata + stage * STAGEB;
        const uint32_t Ahi = st;
        const uint32_t Alo = st + TILEB;
        const uint32_t Bhi = st + 2 * TILEB;
        const uint32_t Blo = st + 3 * TILEB;

        #pragma unroll
        for (int kk = 0; kk < 2; kk++) {      // two k16 halves of BK=32
            uint32_t bh[4][2], bl[4][2];
            #pragma unroll
            for (int q = 0; q < 2; q++) {
                uint32_t r[4];
                ldsm4(r, Bhi + boff[kk][q]);
                bh[2*q][0] = r[0]; bh[2*q][1] = r[1]; bh[2*q+1][0] = r[2]; bh[2*q+1][1] = r[3];
                ldsm4(r, Blo + boff[kk][q]);
                bl[2*q][0] = r[0]; bl[2*q][1] = r[1]; bl[2*q+1][0] = r[2]; bl[2*q+1][1] = r[3];
            }
            #pragma unroll
            for (int mt = 0; mt < 4; mt++) {
                uint32_t ah[4], al[4];
                ldsm4(ah, Ahi + aoff[kk][mt]);
                ldsm4(al, Alo + aoff[kk][mt]);
                #pragma unroll
                for (int nt = 0; nt < 4; nt++) {
                    mma16816(acc[mt][nt], ah, bh[nt]);
                    mma16816(acc[mt][nt], ah, bl[nt]);
                    mma16816(acc[mt][nt], al, bh[nt]);
                }
            }
        }
        stage = (stage == STAGES - 1) ? 0 : stage + 1;
        nstage = (nstage == STAGES - 1) ? 0 : nstage + 1;
    }
    __syncthreads();

    // epilogue: fused squared-distance row-min
    #pragma unroll
    for (int mt = 0; mt < 4; mt++) {
        #pragma unroll
        for (int h = 0; h < 2; h++) {
            const int lrow = warp_m + mt * 16 + (lane >> 2) + h * 8;
            float mn = __int_as_float(0x7f800000);
            #pragma unroll
            for (int nt = 0; nt < 4; nt++) {
                #pragma unroll
                for (int e = 0; e < 2; e++) {
                    const int col = warp_n + nt * 8 + (lane & 3) * 2 + e;
                    mn = fminf(mn, fmaf(-2.0f, acc[mt][nt][h * 2 + e], sy[col]));
                }
            }
            mn = fminf(mn, __shfl_xor_sync(0xffffffffu, mn, 1));
            mn = fminf(mn, __shfl_xor_sync(0xffffffffu, mn, 2));
            if ((lane & 3) == 0) {
                float s = fmaxf(g_xsq[bm + lrow] + mn, 0.0f);
                atomicMin(&rowmin[lrow], __float_as_uint(s));
            }
        }
    }
    __syncthreads();
    if (tid < 128) atomicMin(&g_min[bm + tid], rowmin[tid]);
}

// ---------------------------------------------------------------------------
// Kernel 3: argmax over min squared distances (tie-break lowest index)
// ---------------------------------------------------------------------------
__global__ void kc_argmax_kernel(float* __restrict__ out) {
    const int tid = threadIdx.x;  // 1024
    unsigned long long best = 0ull;
    for (int i = tid; i < NROWS; i += 1024) {
        unsigned long long key = ((unsigned long long)g_min[i] << 32) |
                                 (unsigned long long)(0xffffffffu - (unsigned)i);
        if (key > best) best = key;
    }
    #pragma unroll
    for (int o = 16; o > 0; o >>= 1) {
        unsigned long long v = __shfl_down_sync(0xffffffffu, best, o);
        if (v > best) best = v;
    }
    __shared__ unsigned long long sh[32];
    if ((tid & 31) == 0) sh[tid >> 5] = best;
    __syncthreads();
    if (tid < 32) {
        best = sh[tid];
        #pragma unroll
        for (int o = 16; o > 0; o >>= 1) {
            unsigned long long v = __shfl_down_sync(0xffffffffu, best, o);
            if (v > best) best = v;
        }
        if (tid == 0) {
            unsigned int vbits = (unsigned int)(best >> 32);
            int idx = (int)(0xffffffffu - (unsigned int)(best & 0xffffffffu));
            out[0] = sqrtf(__uint_as_float(vbits));
            out[1] = (float)idx;
        }
    }
}

// ---------------------------------------------------------------------------
extern "C" void kernel_launch(void* const* d_in, const int* in_sizes, int n_in,
                              void* d_out, int out_size) {
    const float* x = (const float*)d_in[0];
    const float* y = (const float*)d_in[1];
    float* out = (float*)d_out;

    cudaFuncSetAttribute(kc_gemm_kernel,
                         cudaFuncAttributeMaxDynamicSharedMemorySize, SM_TOTAL);

    kc_prep_kernel<<<NROWS, 128>>>(x, y);

    dim3 grid(MROWS / 128, NROWS / 128);
    kc_gemm_kernel<<<grid, 256, SM_TOTAL>>>();

    kc_argmax_kernel<<<1, 1024>>>(out);
}